// round 16
// baseline (speedup 1.0000x reference)
#include <cuda_runtime.h>
#include <cuda_fp16.h>
#include <cstdint>

// ---------------- problem constants ----------------
#define B_SZ   8
#define T_LEN  4096
#define D_INP  256
#define D_OUTP 256
#define N_ST   512
#define M_TOT  (B_SZ * T_LEN)      // 32768
#define NBU    (2 * N_ST)          // 1024
#define KCAT   (NBU + D_INP)       // 1280
#define CHUNK  128
#define NCHUNK (T_LEN / CHUNK)     // 32

// ---------------- device scratch ----------------
// A2 layout: cols [0,1024) = X interleaved (2n = xr_n, 2n+1 = xi_n), cols [1024,1280) = u
__device__ __half g_A2[(size_t)M_TOT * KCAT];
__device__ __half g_B1[NBU * D_INP];             // gamma-scaled B, interleaved rows
__device__ __half g_W2[D_OUTP * KCAT];           // K-interleaved [2Cr/-2Ci | D]
__device__ float2 g_lam  [N_ST];
__device__ float2 g_lam64[N_ST];                 // lam^64
__device__ float2 g_lamL [N_ST];                 // lam^128
__device__ float2 g_F    [B_SZ * NCHUNK * N_ST];
__device__ float2 g_carry[B_SZ * NCHUNK * N_ST];

// ---------------- helpers ----------------
__device__ __forceinline__ uint32_t smem_u32(const void* p) {
    uint32_t a;
    asm("{ .reg .u64 t; cvta.to.shared.u64 t, %1; cvt.u32.u64 %0, t; }" : "=r"(a) : "l"(p));
    return a;
}

#define CP_ASYNC16(dst, src) \
    asm volatile("cp.async.cg.shared.global [%0], [%1], 16;" :: "r"(dst), "l"(src))
#define CP_COMMIT() asm volatile("cp.async.commit_group;")
#define CP_WAIT1()  asm volatile("cp.async.wait_group 1;")
#define CP_WAIT0()  asm volatile("cp.async.wait_group 0;")

#define LDSM4(r0, r1, r2, r3, addr) \
    asm volatile("ldmatrix.sync.aligned.m8n8.x4.shared.b16 {%0,%1,%2,%3}, [%4];" \
        : "=r"(r0), "=r"(r1), "=r"(r2), "=r"(r3) : "r"(addr))

#define MMA16816(d, a, b0, b1) \
    asm volatile("mma.sync.aligned.m16n8k16.row.col.f32.f16.f16.f32 " \
        "{%0,%1,%2,%3}, {%4,%5,%6,%7}, {%8,%9}, {%0,%1,%2,%3};" \
        : "+f"(d[0]), "+f"(d[1]), "+f"(d[2]), "+f"(d[3]) \
        : "r"(a[0]), "r"(a[1]), "r"(a[2]), "r"(a[3]), "r"(b0), "r"(b1))

// ---------------- merged setup + weight prep + u conversion ----------------
#define B1_ELEMS (NBU * D_INP)
#define W2_ELEMS (D_OUTP * KCAT)
#define U_CHUNKS (M_TOT * D_INP / 4)
__global__ void k_prep(const float* __restrict__ nu_log,
                       const float* __restrict__ theta_log,
                       const float* __restrict__ gamma_log,
                       const float* __restrict__ Br,
                       const float* __restrict__ Bi,
                       const float* __restrict__ Cr,
                       const float* __restrict__ Ci,
                       const float* __restrict__ Dm,
                       const float* __restrict__ u) {
    int idx = blockIdx.x * blockDim.x + threadIdx.x;
    if (idx < U_CHUNKS) {
        int m = idx / (D_INP / 4), i = (idx % (D_INP / 4)) * 4;
        float4 v = *(const float4*)(u + (size_t)m * D_INP + i);
        __half2 h0 = __floats2half2_rn(v.x, v.y);
        __half2 h1 = __floats2half2_rn(v.z, v.w);
        __half2* dst = (__half2*)(g_A2 + (size_t)m * KCAT + NBU + i);
        dst[0] = h0;
        dst[1] = h1;
        return;
    }
    int r = idx - U_CHUNKS;
    if (r < N_ST) {
        int n = r;
        float lm = expf(-expf(nu_log[n]));
        float th = expf(theta_log[n]);
        float2 lam = make_float2(lm * cosf(th), lm * sinf(th));
        g_lam[n] = lam;
        float2 p = lam;
#pragma unroll
        for (int i = 0; i < 6; i++) {
            float2 q;
            q.x = p.x * p.x - p.y * p.y;
            q.y = 2.0f * p.x * p.y;
            p = q;
        }
        g_lam64[n] = p;                      // lam^64
        float2 q;
        q.x = p.x * p.x - p.y * p.y;
        q.y = 2.0f * p.x * p.y;
        g_lamL[n] = q;                       // lam^128
    } else if (r < N_ST + B1_ELEMS) {
        int j = r - N_ST;
        int nn = j / D_INP, i = j % D_INP;
        int n = nn >> 1;
        float g = expf(gamma_log[n]);
        float v = g * (((nn & 1) == 0) ? Br[n * D_INP + i] : Bi[n * D_INP + i]);
        g_B1[j] = __float2half_rn(v);
    } else if (r < N_ST + B1_ELEMS + W2_ELEMS) {
        int j = r - N_ST - B1_ELEMS;
        int o = j / KCAT, k = j % KCAT;
        float v;
        if (k < NBU) {
            int n = k >> 1;
            v = ((k & 1) == 0) ? 2.0f * Cr[o * N_ST + n] : -2.0f * Ci[o * N_ST + n];
        } else {
            v = Dm[o * D_INP + (k - NBU)];
        }
        g_W2[j] = __float2half_rn(v);
    }
}

// ---------------- GEMM mainloop: CTA 128(M) x 128(N), BK=64, 256 threads ----------------
// 8 warps as 2(m) x 4(n); warp tile 64x32; mma.m16n8k16; acc[4][4][4].
// 3-stage cp.async pipeline (2 in flight), ONE __syncthreads per 64-wide k-chunk.
#define NTHREADS 256
#define BK       64
#define PADK     72                       // padded k-stride (elems) -> 144 B rows
#define TILE_T_B (128 * PADK * 2)         // 18432 B per tile (A or B)
#define STAGE_B  (2 * TILE_T_B)           // 36864 B
#define STAGES   3
#define SMEM_GEMM (STAGES * STAGE_B)      // 110592 B

__device__ __forceinline__ void gemm_mainloop(
    uint32_t sb, const __half* A0, const __half* B0,
    int K, int lda, int ldb, float acc[4][4][4],
    int tid, int wm, int wn, int lid) {

    const int NC = K / BK;

    auto issue_load = [&](int c) {
        const int s = c % STAGES;
        const uint32_t stb = sb + s * STAGE_B;
        const int k0 = c * BK;
#pragma unroll
        for (int r = 0; r < 4; r++) {                // A: 1024 chunks of 16B
            int idx = tid + r * NTHREADS;
            int row = idx >> 3, ch = idx & 7;
            uint32_t soff = (uint32_t)(row * (PADK * 2) + ch * 16);
            CP_ASYNC16(stb + soff, A0 + (size_t)row * lda + k0 + ch * 8);
        }
#pragma unroll
        for (int r = 0; r < 4; r++) {                // B: 1024 chunks
            int idx = tid + r * NTHREADS;
            int row = idx >> 3, ch = idx & 7;
            uint32_t soff = (uint32_t)(row * (PADK * 2) + ch * 16);
            CP_ASYNC16(stb + TILE_T_B + soff, B0 + (size_t)row * ldb + k0 + ch * 8);
        }
        CP_COMMIT();
    };

    const int aRow = lid & 15;
    const int aCol = (lid >> 4) << 3;
    const int bRow = (lid & 7) + ((lid >> 4) << 3);
    const int bCol = ((lid >> 3) & 1) << 3;

    issue_load(0);
    issue_load(1);

    for (int c = 0; c < NC; c++) {
        CP_WAIT1();
        __syncthreads();                   // single barrier per k-chunk
        if (c + 2 < NC) issue_load(c + 2);
        else            CP_COMMIT();       // keep group-count invariant

        const uint32_t stb = sb + (c % STAGES) * STAGE_B;
        const uint32_t sA = stb;
        const uint32_t sB = stb + TILE_T_B;

#pragma unroll
        for (int kk = 0; kk < BK; kk += 16) {
            uint32_t a[4][4], b[2][4];
#pragma unroll
            for (int mf = 0; mf < 4; mf++) {
                uint32_t ad = sA + (uint32_t)((wm * 64 + mf * 16 + aRow) * (PADK * 2) + (kk + aCol) * 2);
                LDSM4(a[mf][0], a[mf][1], a[mf][2], a[mf][3], ad);
            }
#pragma unroll
            for (int p = 0; p < 2; p++) {
                uint32_t bd = sB + (uint32_t)((wn * 32 + p * 16 + bRow) * (PADK * 2) + (kk + bCol) * 2);
                LDSM4(b[p][0], b[p][1], b[p][2], b[p][3], bd);
            }
#pragma unroll
            for (int mf = 0; mf < 4; mf++)
#pragma unroll
                for (int nf = 0; nf < 4; nf++)
                    MMA16816(acc[mf][nf], a[mf], b[nf >> 1][(nf & 1) * 2], b[nf >> 1][(nf & 1) * 2 + 1]);
        }
    }
    CP_WAIT0();
}

// ---------------- GEMM1 + fused two-phase chunk-local scan ----------------
#define SCAN_STRIDE 136

__global__ __launch_bounds__(NTHREADS, 2)
void gemm1_scan(const __half* __restrict__ A,
                const __half* __restrict__ B) {
    extern __shared__ char smem[];
    const uint32_t sb = smem_u32(smem);
    const int tid = threadIdx.x;
    const int wid = tid >> 5, lid = tid & 31;
    const int m0 = blockIdx.y * 128;
    const int n0 = blockIdx.x * 128;
    const int wm = wid >> 2, wn = wid & 3;

    float acc[4][4][4];
#pragma unroll
    for (int i = 0; i < 4; i++)
#pragma unroll
        for (int j = 0; j < 4; j++)
#pragma unroll
            for (int q = 0; q < 4; q++) acc[i][j][q] = 0.0f;

    gemm_mainloop(sb, A + (size_t)m0 * KCAT, B + (size_t)n0 * D_INP,
                  D_INP, KCAT, D_INP, acc, tid, wm, wn, lid);

    __syncthreads();            // drain: pipeline smem dead, reuse for scan buffer

    float* sc = (float*)smem;   // [128][SCAN_STRIDE]
    const int gid = lid >> 2, tig = lid & 3;
#pragma unroll
    for (int mf = 0; mf < 4; mf++) {
        const int row = wm * 64 + mf * 16 + gid;
#pragma unroll
        for (int nf = 0; nf < 4; nf++) {
            const int col = wn * 32 + nf * 8 + tig * 2;
            *(float2*)(sc + row * SCAN_STRIDE + col) =
                make_float2(acc[mf][nf][0], acc[mf][nf][1]);
            *(float2*)(sc + (row + 8) * SCAN_STRIDE + col) =
                make_float2(acc[mf][nf][2], acc[mf][nf][3]);
        }
    }
    __syncthreads();

    // Phase A: two 64-step segment scans (threads 0..127)
    if (tid < 128) {
        const int s = tid & 63;                 // state within tile
        const int seg = tid >> 6;               // 0: t=0..63 (final), 1: t=64..127 (partial)
        const int np = (n0 >> 1) + s;
        const float2 lam = g_lam[np];
        float xr = 0.0f, xi = 0.0f;
        float* p = sc + seg * 64 * SCAN_STRIDE + 2 * s;
        __half* out = g_A2 + (size_t)(m0 + seg * 64) * KCAT + 2 * np;
#pragma unroll 4
        for (int t = 0; t < 64; t++) {
            float2 bu = *(const float2*)p;
            float nxr = fmaf(lam.x, xr, fmaf(-lam.y, xi, bu.x));
            float nxi = fmaf(lam.x, xi, fmaf(lam.y, xr, bu.y));
            xr = nxr; xi = nxi;
            if (seg == 0) {
                *(__half2*)(out + (size_t)t * KCAT) = __floats2half2_rn(xr, xi);
                *(float2*)p = make_float2(xr, xi);   // x63 needed by phase B
            } else {
                *(float2*)p = make_float2(xr, xi);   // partial, corrected in phase B
            }
            p += SCAN_STRIDE;
        }
    }
    __syncthreads();

    // Phase B: combine x_t += lam^(t-63)*x63 for t in 64..127 (threads 0..63)
    if (tid < 64) {
        const int s = tid;
        const int np = (n0 >> 1) + s;
        const float2 lam = g_lam[np];
        float2 x63 = *(const float2*)(sc + 63 * SCAN_STRIDE + 2 * s);
        float fr = x63.x, fi = x63.y;              // running lam^(t-63) * x63
        const int b = m0 >> 12;
        const int c = (m0 & (T_LEN - 1)) >> 7;
        __half* out = g_A2 + (size_t)(m0 + 64) * KCAT + 2 * np;
        float xr = 0.0f, xi = 0.0f;
#pragma unroll 4
        for (int t = 0; t < 64; t++) {
            float nfr = fr * lam.x - fi * lam.y;
            float nfi = fr * lam.y + fi * lam.x;
            fr = nfr; fi = nfi;
            float2 xp = *(const float2*)(sc + (64 + t) * SCAN_STRIDE + 2 * s);
            xr = xp.x + fr;
            xi = xp.y + fi;
            *(__half2*)(out + (size_t)t * KCAT) = __floats2half2_rn(xr, xi);
        }
        g_F[(b * NCHUNK + c) * N_ST + np] = make_float2(xr, xi);
    }
}

// ---------------- GEMM2: y[M,256] = A2 @ W2^T ----------------
__global__ __launch_bounds__(NTHREADS, 2)
void gemm2_out(const __half* __restrict__ A,
               const __half* __restrict__ B,
               float* __restrict__ C) {
    extern __shared__ char smem[];
    const uint32_t sb = smem_u32(smem);
    const int tid = threadIdx.x;
    const int wid = tid >> 5, lid = tid & 31;
    const int m0 = blockIdx.y * 128;
    const int n0 = blockIdx.x * 128;
    const int wm = wid >> 2, wn = wid & 3;

    float acc[4][4][4];
#pragma unroll
    for (int i = 0; i < 4; i++)
#pragma unroll
        for (int j = 0; j < 4; j++)
#pragma unroll
            for (int q = 0; q < 4; q++) acc[i][j][q] = 0.0f;

    gemm_mainloop(sb, A + (size_t)m0 * KCAT, B + (size_t)n0 * KCAT,
                  KCAT, KCAT, KCAT, acc, tid, wm, wn, lid);

    const int gid = lid >> 2, tig = lid & 3;
#pragma unroll
    for (int mf = 0; mf < 4; mf++) {
        const int row = m0 + wm * 64 + mf * 16 + gid;
#pragma unroll
        for (int nf = 0; nf < 4; nf++) {
            const int col = n0 + wn * 32 + nf * 8 + tig * 2;
            __stcs((float2*)(C + (size_t)row * D_OUTP + col),
                   make_float2(acc[mf][nf][0], acc[mf][nf][1]));
            __stcs((float2*)(C + (size_t)(row + 8) * D_OUTP + col),
                   make_float2(acc[mf][nf][2], acc[mf][nf][3]));
        }
    }
}

// ---------------- chunk-level prefix: Kogge-Stone warp scan ----------------
__global__ void k_chunk_prefix() {
    int gid = blockIdx.x * blockDim.x + threadIdx.x;
    int w = gid >> 5;                       // (b, n) index
    int lane = gid & 31;
    if (w >= B_SZ * N_ST) return;
    int n = w & (N_ST - 1);
    int b = w >> 9;

    float2 lamL = g_lamL[n];
    float2 f = g_F[(b * NCHUNK + lane) * N_ST + n];
    float ar = lamL.x, ai = lamL.y;         // A (lam^128)
    float br = f.x,    bi = f.y;            // B

#pragma unroll
    for (int d = 1; d < 32; d <<= 1) {
        float par = __shfl_up_sync(0xFFFFFFFFu, ar, d);
        float pai = __shfl_up_sync(0xFFFFFFFFu, ai, d);
        float pbr = __shfl_up_sync(0xFFFFFFFFu, br, d);
        float pbi = __shfl_up_sync(0xFFFFFFFFu, bi, d);
        if (lane >= d) {
            float nbr = ar * pbr - ai * pbi + br;
            float nbi = ar * pbi + ai * pbr + bi;
            float nar = ar * par - ai * pai;
            float nai = ar * pai + ai * par;
            ar = nar; ai = nai; br = nbr; bi = nbi;
        }
    }
    float cr = __shfl_up_sync(0xFFFFFFFFu, br, 1);
    float ci = __shfl_up_sync(0xFFFFFFFFu, bi, 1);
    if (lane == 0) { cr = 0.0f; ci = 0.0f; }
    g_carry[(b * NCHUNK + lane) * N_ST + n] = make_float2(cr, ci);
}

// ---------------- carry correction: x_t += lam^{t+1} * carry ----------------
__global__ void k_correct() {
    int id = blockIdx.x * blockDim.x + threadIdx.x;
    if (id >= B_SZ * NCHUNK * (N_ST / 2) * 2) return;
    int sp = id & (N_ST / 2 - 1);             // state pair 0..255
    int h  = (id >> 8) & 1;                   // t-half
    int c  = (id >> 9) & (NCHUNK - 1);
    int b  = id >> 14;
    if (c == 0) return;                       // carry is zero for chunk 0
    const int np0 = 2 * sp, np1 = 2 * sp + 1;
    const int cbase = (b * NCHUNK + c) * N_ST;
    float2 ca = g_carry[cbase + np0];
    float2 cb = g_carry[cbase + np1];
    float2 la = g_lam[np0];
    float2 lb = g_lam[np1];
    float ar = ca.x, ai = ca.y;
    float br = cb.x, bi = cb.y;
    if (h) {                                   // seed with lam^64
        float2 pa = g_lam64[np0], pb = g_lam64[np1];
        float t0 = ar * pa.x - ai * pa.y;
        ai = ar * pa.y + ai * pa.x; ar = t0;
        float t1 = br * pb.x - bi * pb.y;
        bi = br * pb.y + bi * pb.x; br = t1;
    }
    __half2* xp = (__half2*)(g_A2 + ((size_t)(b * T_LEN + c * CHUNK + h * 64)) * KCAT + 4 * sp);
    const int stride2 = KCAT / 2;             // __half2 stride per t
#pragma unroll 4
    for (int t = 0; t < 64; t++) {
        float nar = ar * la.x - ai * la.y;
        float nai = ar * la.y + ai * la.x;
        ar = nar; ai = nai;
        float nbr = br * lb.x - bi * lb.y;
        float nbi = br * lb.y + bi * lb.x;
        br = nbr; bi = nbi;
        uint2* up = (uint2*)(xp + (size_t)t * stride2);
        uint2 raw = *up;
        __half2 v0 = *(__half2*)&raw.x;
        __half2 v1 = *(__half2*)&raw.y;
        float2 x0 = __half22float2(v0);
        float2 x1 = __half22float2(v1);
        __half2 o0 = __floats2half2_rn(x0.x + ar, x0.y + ai);
        __half2 o1 = __floats2half2_rn(x1.x + br, x1.y + bi);
        uint2 out;
        out.x = *(uint32_t*)&o0;
        out.y = *(uint32_t*)&o1;
        *up = out;
    }
}

// ---------------- launch ----------------
extern "C" void kernel_launch(void* const* d_in, const int* in_sizes, int n_in,
                              void* d_out, int out_size) {
    const float* u_in      = (const float*)d_in[0];
    const float* nu_log    = (const float*)d_in[1];
    const float* theta_log = (const float*)d_in[2];
    const float* gamma_log = (const float*)d_in[3];
    const float* B_real    = (const float*)d_in[4];
    const float* B_imag    = (const float*)d_in[5];
    const float* C_real    = (const float*)d_in[6];
    const float* C_imag    = (const float*)d_in[7];
    const float* Dm        = (const float*)d_in[8];
    float* y = (float*)d_out;

    __half *a2, *b1, *w2;
    cudaGetSymbolAddress((void**)&a2, g_A2);
    cudaGetSymbolAddress((void**)&b1, g_B1);
    cudaGetSymbolAddress((void**)&w2, g_W2);

    cudaFuncSetAttribute(gemm1_scan,
                         cudaFuncAttributeMaxDynamicSharedMemorySize, SMEM_GEMM);
    cudaFuncSetAttribute(gemm2_out,
                         cudaFuncAttributeMaxDynamicSharedMemorySize, SMEM_GEMM);

    // merged setup + weight prep + u conversion (one launch)
    k_prep<<<(U_CHUNKS + N_ST + B1_ELEMS + W2_ELEMS + 255) / 256, 256>>>(
        nu_log, theta_log, gamma_log, B_real, B_imag, C_real, C_imag, Dm, u_in);

    // GEMM1 + chunk-local scan: writes X_local (fp16) into A2 and chunk finals
    {
        dim3 grid(NBU / 128, M_TOT / 128);
        gemm1_scan<<<grid, NTHREADS, SMEM_GEMM>>>(a2 + NBU, b1);
    }

    // chunk prefix (warp scan) + carry correction
    k_chunk_prefix<<<(B_SZ * N_ST * 32 + 255) / 256, 256>>>();
    k_correct<<<(B_SZ * NCHUNK * N_ST + 255) / 256, 256>>>();

    // GEMM 2: y[M, 256] = [X | u] @ W2^T, K=1280
    {
        dim3 grid(D_OUTP / 128, M_TOT / 128);
        gemm2_out<<<grid, NTHREADS, SMEM_GEMM>>>(a2, w2, y);
    }
}